// round 5
// baseline (speedup 1.0000x reference)
#include <cuda_runtime.h>

#define BB 64
#define SS 512
#define HH 1024
#define KK 7
#define NCHUNK 16
#define RPB 32
#define NTILE (BB * NCHUNK)   // 1024
#define GRID 512

typedef unsigned long long ull;

// scratch (allocation-free rule: __device__ globals)
__device__ float g_M[NTILE * KK * KK];  // chunk transfer matrices (log2)
__device__ float g_nump[NTILE];         // numerator partials
__device__ int   g_cntp[NTILE];         // mask-count partials
__device__ float g_em0[BB * KK];        // emissions row 0 per batch
__device__ unsigned int g_cnt = 0;      // self-resetting completion counter

// ---------------------------------------------------------------------------
// fast math helpers
// ---------------------------------------------------------------------------
__device__ __forceinline__ float ex2f(float x) {
    float y; asm("ex2.approx.f32 %0, %1;" : "=f"(y) : "f"(x)); return y;
}
__device__ __forceinline__ float lg2f(float x) {
    float y; asm("lg2.approx.f32 %0, %1;" : "=f"(y) : "f"(x)); return y;
}
__device__ __forceinline__ ull pk2(float lo, float hi) {
    ull r; asm("mov.b64 %0, {%1,%2};" : "=l"(r) : "f"(lo), "f"(hi)); return r;
}
__device__ __forceinline__ void upk2(ull p, float& lo, float& hi) {
    asm("mov.b64 {%0,%1}, %2;" : "=f"(lo), "=f"(hi) : "l"(p));
}
__device__ __forceinline__ ull fma2(ull a, ull b, ull c) {
    ull d; asm("fma.rn.f32x2 %0, %1, %2, %3;" : "=l"(d) : "l"(a), "l"(b), "l"(c));
    return d;
}

// ---------------------------------------------------------------------------
// dtype-width detection (harness may canonicalize bool/int64)
// ---------------------------------------------------------------------------
__device__ __forceinline__ int detect_mask_w(const unsigned char* m) {
    unsigned int or123 = 0, or4 = 0;
#pragma unroll
    for (int off = 0; off < 64; off++) {
        unsigned char v = m[off];
        if (off & 3) or123 |= v;
        else if ((off & 7) == 4) or4 |= v;
    }
    if (or123) return 1;
    return or4 ? 4 : 8;
}
__device__ __forceinline__ int detect_gt_w(const void* gt) {
    const int* v = (const int*)gt;
    int orv = 0;
#pragma unroll
    for (int q = 0; q < 64; q++) orv |= v[2 * q + 1];
    return (orv == 0) ? 2 : 1; // stride in 32-bit words
}

// ---------------------------------------------------------------------------
// THE kernel: persistent; each block handles tiles bid, bid+512. Per tile:
// emissions GEMV (DRAM-bound), chunk transfer matrix, numerator partial.
// Last-finishing block does the global combine and writes the scalar.
// ---------------------------------------------------------------------------
__global__ __launch_bounds__(128, 4) void k_all(const float4* __restrict__ x4,
                                                const float* __restrict__ W,
                                                const float* __restrict__ bias,
                                                const void* __restrict__ gt,
                                                const unsigned char* __restrict__ mask,
                                                const float* __restrict__ start_t,
                                                const float* __restrict__ end_t,
                                                const float* __restrict__ trans,
                                                float* __restrict__ out) {
    const int t = threadIdx.x;
    const int lane = t & 31, warp = t >> 5;
    const int bid = blockIdx.x;
    const float L2E = 1.4426950408889634f, LN2 = 0.6931471805599453f;

    __shared__ float wsum[4][RPB][7];
    __shared__ float em_s[RPB][8];
    __shared__ int msk_s[RPB];
    __shared__ int s_mw, s_gw, s_isLast;
    __shared__ float s_fin[4];

    if (t == 0) { s_mw = detect_mask_w(mask); s_gw = detect_gt_w(gt); }

    // ---- W slice (56 floats) into registers, packed f32x2 ----
    ull w01[8], w23[8], w45[8];
    float w6[8];
#pragma unroll
    for (int jj = 0; jj < 2; jj++) {
        const float4* wp4 = (const float4*)(W + (t * 4 + jj * 512) * 7);
        float wb[28];
#pragma unroll
        for (int q4 = 0; q4 < 7; q4++) {
            float4 v = wp4[q4];
            wb[q4 * 4 + 0] = v.x; wb[q4 * 4 + 1] = v.y;
            wb[q4 * 4 + 2] = v.z; wb[q4 * 4 + 3] = v.w;
        }
#pragma unroll
        for (int q = 0; q < 4; q++) {
            int s = jj * 4 + q;
            w01[s] = pk2(wb[q * 7 + 0], wb[q * 7 + 1]);
            w23[s] = pk2(wb[q * 7 + 2], wb[q * 7 + 3]);
            w45[s] = pk2(wb[q * 7 + 4], wb[q * 7 + 5]);
            w6[s] = wb[q * 7 + 6];
        }
    }
    __syncthreads();
    const int mw = s_mw, gw = s_gw;

#define DO_ROW(RR, X0, X1)                                                      \
    {                                                                           \
        float xq[8] = {X0.x, X0.y, X0.z, X0.w, X1.x, X1.y, X1.z, X1.w};         \
        ull c01 = 0, c23 = 0, c45 = 0;                                          \
        float c6 = 0.f;                                                         \
        _Pragma("unroll") for (int s = 0; s < 8; s++) {                         \
            ull xx = pk2(xq[s], xq[s]);                                         \
            c01 = fma2(xx, w01[s], c01);                                        \
            c23 = fma2(xx, w23[s], c23);                                        \
            c45 = fma2(xx, w45[s], c45);                                        \
            c6 = fmaf(xq[s], w6[s], c6);                                        \
        }                                                                       \
        float a[7];                                                             \
        upk2(c01, a[0], a[1]); upk2(c23, a[2], a[3]); upk2(c45, a[4], a[5]);    \
        a[6] = c6;                                                              \
        float tt[7];                                                            \
        _Pragma("unroll") for (int k = 0; k < 7; k++)                           \
            tt[k] = __shfl_xor_sync(0xffffffffu, a[k], 16);                     \
        bool hh = (lane & 16);                                                  \
        float v0 = hh ? a[4] + tt[4] : a[0] + tt[0];                            \
        float v1 = hh ? a[5] + tt[5] : a[1] + tt[1];                            \
        float v2 = hh ? a[6] + tt[6] : a[2] + tt[2];                            \
        float v3 = hh ? 0.f : a[3] + tt[3];                                     \
        float s0 = __shfl_xor_sync(0xffffffffu, v0, 8);                         \
        float s1 = __shfl_xor_sync(0xffffffffu, v1, 8);                         \
        float s2 = __shfl_xor_sync(0xffffffffu, v2, 8);                         \
        float s3 = __shfl_xor_sync(0xffffffffu, v3, 8);                         \
        bool b3p = (lane & 8);                                                  \
        float u0 = b3p ? v2 + s2 : v0 + s0;                                     \
        float u1 = b3p ? v3 + s3 : v1 + s1;                                     \
        float p0 = __shfl_xor_sync(0xffffffffu, u0, 4);                         \
        float p1 = __shfl_xor_sync(0xffffffffu, u1, 4);                         \
        float wv = (lane & 4) ? u1 + p1 : u0 + p0;                              \
        wv += __shfl_xor_sync(0xffffffffu, wv, 2);                              \
        wv += __shfl_xor_sync(0xffffffffu, wv, 1);                              \
        int k7 = (lane >> 2) & 7;                                               \
        if (((lane & 3) == 0) && (k7 < 7)) wsum[warp][RR][k7] = wv;             \
    }

    // ---- initial prefetch: rows 0..3 of first tile ----
    float4 buf[4][2];
    {
        const long r0 = (long)bid * RPB;
#pragma unroll
        for (int u = 0; u < 4; u++) {
            buf[u][0] = x4[(r0 + u) * 256 + t];
            buf[u][1] = x4[(r0 + u) * 256 + 128 + t];
        }
    }

    for (int tile = bid; tile < NTILE; tile += GRID) {
        const int b = tile >> 4, c = tile & 15;
        const long row0 = (long)tile * RPB;

#pragma unroll 1
        for (int rb = 0; rb < RPB; rb += 4) {
#pragma unroll
            for (int u = 0; u < 4; u++) {
                const int r = rb + u;
                float4 X0 = buf[u][0], X1 = buf[u][1];
                // prefetch logical row r+4 (spills into next tile)
                const int pr = r + 4;
                long prow;
                bool valid;
                if (pr < RPB) { prow = row0 + pr; valid = true; }
                else {
                    const int nt = tile + GRID;
                    prow = (long)nt * RPB + (pr - RPB);
                    valid = (nt < NTILE);
                }
                if (valid) {
                    buf[u][0] = x4[prow * 256 + t];
                    buf[u][1] = x4[prow * 256 + 128 + t];
                }
                DO_ROW(r, X0, X1);
            }
        }
        __syncthreads();

        // ---- combine warp partials -> em_s; fill msk_s; write em0 ----
        for (int idx = t; idx < RPB * 7; idx += 128) {
            int r = idx / 7, k = idx - r * 7;
            float e = wsum[0][r][k] + wsum[1][r][k] + wsum[2][r][k] + wsum[3][r][k] + bias[k];
            em_s[r][k] = e;
            if (c == 0 && idx < 7) g_em0[b * 7 + idx] = e;
        }
        if (t < RPB) msk_s[t] = mask[((long)b * SS + c * RPB + t) * mw] ? 1 : 0;
        __syncthreads();

        // ---- warps 0-1: chunk transfer matrix (scaled forward) ----
        if (warp < 2) {
            const int j = lane & 7;
            const int i = (lane >> 3) + warp * 4;
            const bool act = (j < 7) && (i < 7);
            const int jj = (j < 7) ? j : 0;
            float Tr[7];
#pragma unroll
            for (int k = 0; k < 7; k++)
                Tr[k] = act ? ex2f(trans[k * 7 + jj] * L2E) : 0.f;

            float v = (act && i == j) ? 1.f : 0.f;
            int mexp = 0;
            const int lt0 = (c == 0) ? 1 : 0;
            for (int lt = lt0; lt < RPB; lt++) {
                float e = ex2f(em_s[lt][jj] * L2E);
                int mk = msk_s[lt];
                float nv = 0.f;
#pragma unroll
                for (int k = 0; k < 7; k++)
                    nv = fmaf(__shfl_sync(0xffffffffu, v, k, 8), Tr[k], nv);
                if (mk) v = nv * e;
                if (((lt & 3) == 3) || (lt == RPB - 1)) {
                    float rs = v;
                    rs += __shfl_xor_sync(0xffffffffu, rs, 4, 8);
                    rs += __shfl_xor_sync(0xffffffffu, rs, 2, 8);
                    rs += __shfl_xor_sync(0xffffffffu, rs, 1, 8);
                    int eb = ((__float_as_int(rs) >> 23) & 255) - 127;
                    eb = (rs > 0.f) ? eb : 0;
                    v *= __int_as_float((127 - eb) << 23); // * 2^-eb
                    mexp += eb;
                }
            }
            if (act)
                g_M[((long)tile * 7 + i) * 7 + j] = (float)mexp + lg2f(v);
        }

        // ---- warp 2: numerator + count partial ----
        if (warp == 2) {
            const int s = c * RPB + lane;
            const int m = msk_s[lane];
            const int gc = ((const int*)gt)[((long)b * SS + s) * gw];
            float contrib;
            if (s == 0) {
                contrib = start_t[gc] + em_s[0][gc];
            } else {
                const int gp = ((const int*)gt)[((long)b * SS + s - 1) * gw];
                contrib = m ? (trans[gp * 7 + gc] + em_s[lane][gc]) : 0.f;
            }
            float sum = contrib;
            int cnt = m;
#pragma unroll
            for (int off = 16; off; off >>= 1) {
                sum += __shfl_xor_sync(0xffffffffu, sum, off);
                cnt += __shfl_xor_sync(0xffffffffu, cnt, off);
            }
            if (lane == 0) { g_nump[tile] = sum; g_cntp[tile] = cnt; }
        }
    }
#undef DO_ROW

    // ---- completion: last block does the global combine ----
    if (t == 0) {
        __threadfence();
        unsigned int old = atomicInc(&g_cnt, GRID - 1);
        s_isLast = (old == GRID - 1) ? 1 : 0;
    }
    __syncthreads();
    if (!s_isLast) return;
    __threadfence();

    // 16 groups of 8 lanes; 2 batch slots x 2 passes = 64 batches
    const int j = t & 7, grp = t >> 3;
    const int jj = (j < 7) ? j : 0;
    float llh = 0.f;

#pragma unroll 1
    for (int pass = 0; pass < 2; pass++) {
        const int bA = grp + pass * 32;
        const int bel = bA + 16;

        float pA = __ldcg(&g_nump[bA * 16 + j]) + __ldcg(&g_nump[bA * 16 + 8 + j]);
        float pB = __ldcg(&g_nump[bel * 16 + j]) + __ldcg(&g_nump[bel * 16 + 8 + j]);
        int cA = __ldcg(&g_cntp[bA * 16 + j]) + __ldcg(&g_cntp[bA * 16 + 8 + j]);
        int cB = __ldcg(&g_cntp[bel * 16 + j]) + __ldcg(&g_cntp[bel * 16 + 8 + j]);
#pragma unroll
        for (int off = 4; off; off >>= 1) {
            pA += __shfl_xor_sync(0xffffffffu, pA, off, 8);
            pB += __shfl_xor_sync(0xffffffffu, pB, off, 8);
            cA += __shfl_xor_sync(0xffffffffu, cA, off, 8);
            cB += __shfl_xor_sync(0xffffffffu, cB, off, 8);
        }

        float aA = (j < 7) ? (start_t[jj] + __ldcg(&g_em0[bA * 7 + jj])) * L2E : -1e30f;
        float aB = (j < 7) ? (start_t[jj] + __ldcg(&g_em0[bel * 7 + jj])) * L2E : -1e30f;

        float MA[7], MB[7], MA2[7], MB2[7];
#pragma unroll
        for (int i2 = 0; i2 < 7; i2++) {
            MA[i2] = __ldcg(&g_M[(((long)bA * 16 + 0) * 7 + i2) * 7 + jj]);
            MB[i2] = __ldcg(&g_M[(((long)bel * 16 + 0) * 7 + i2) * 7 + jj]);
        }

        for (int cc = 0; cc < NCHUNK; cc++) {
            if (cc + 1 < NCHUNK) {
#pragma unroll
                for (int i2 = 0; i2 < 7; i2++) {
                    MA2[i2] = __ldcg(&g_M[(((long)bA * 16 + cc + 1) * 7 + i2) * 7 + jj]);
                    MB2[i2] = __ldcg(&g_M[(((long)bel * 16 + cc + 1) * 7 + i2) * 7 + jj]);
                }
            }
            float mxA = -1e30f, mxB = -1e30f;
            float vvA[7], vvB[7];
#pragma unroll
            for (int i2 = 0; i2 < 7; i2++) {
                vvA[i2] = __shfl_sync(0xffffffffu, aA, i2, 8) + MA[i2];
                vvB[i2] = __shfl_sync(0xffffffffu, aB, i2, 8) + MB[i2];
                mxA = fmaxf(mxA, vvA[i2]);
                mxB = fmaxf(mxB, vvB[i2]);
            }
            float sA = 0.f, sB = 0.f;
#pragma unroll
            for (int i2 = 0; i2 < 7; i2++) {
                sA += ex2f(vvA[i2] - mxA);
                sB += ex2f(vvB[i2] - mxB);
            }
            float nA = mxA + lg2f(sA), nB = mxB + lg2f(sB);
            aA = (j < 7) ? nA : -1e30f;
            aB = (j < 7) ? nB : -1e30f;
#pragma unroll
            for (int i2 = 0; i2 < 7; i2++) { MA[i2] = MA2[i2]; MB[i2] = MB2[i2]; }
        }

        float zA = (j < 7) ? aA + end_t[jj] * L2E : -1e30f;
        float zB = (j < 7) ? aB + end_t[jj] * L2E : -1e30f;
        float mzA = zA, mzB = zB;
#pragma unroll
        for (int off = 4; off; off >>= 1) {
            mzA = fmaxf(mzA, __shfl_xor_sync(0xffffffffu, mzA, off, 8));
            mzB = fmaxf(mzB, __shfl_xor_sync(0xffffffffu, mzB, off, 8));
        }
        float seA = ex2f(zA - mzA), seB = ex2f(zB - mzB);
#pragma unroll
        for (int off = 4; off; off >>= 1) {
            seA += __shfl_xor_sync(0xffffffffu, seA, off, 8);
            seB += __shfl_xor_sync(0xffffffffu, seB, off, 8);
        }
        float denA = (mzA + lg2f(seA)) * LN2;
        float denB = (mzB + lg2f(seB)) * LN2;

        if (j == 0) {
            float numA = pA + end_t[((const int*)gt)[((long)bA * SS + cA - 1) * gw]];
            float numB = pB + end_t[((const int*)gt)[((long)bel * SS + cB - 1) * gw]];
            llh += (numA - denA) + (numB - denB);
        }
    }

    float v = (j == 0) ? llh : 0.f;
    v += __shfl_xor_sync(0xffffffffu, v, 8);
    v += __shfl_xor_sync(0xffffffffu, v, 16);
    if (lane == 0) s_fin[warp] = v;
    __syncthreads();
    if (t == 0)
        out[0] = -(s_fin[0] + s_fin[1] + s_fin[2] + s_fin[3]) / (float)BB;
}

// ---------------------------------------------------------------------------
extern "C" void kernel_launch(void* const* d_in, const int* in_sizes, int n_in,
                              void* d_out, int out_size) {
    const float4* x = (const float4*)d_in[0];
    const void* gt = d_in[1];
    const unsigned char* mask = (const unsigned char*)d_in[2];
    const float* W = (const float*)d_in[3];
    const float* bias = (const float*)d_in[4];
    const float* start_t = (const float*)d_in[5];
    const float* end_t = (const float*)d_in[6];
    const float* trans = (const float*)d_in[7];
    float* out = (float*)d_out;

    k_all<<<GRID, 128>>>(x, W, bias, gt, mask, start_t, end_t, trans, out);
}

// round 6
// speedup vs baseline: 1.2360x; 1.2360x over previous
#include <cuda_runtime.h>

#define BB 64
#define SS 512
#define HH 1024
#define KK 7
#define NCHUNK 16
#define NTILE (BB * NCHUNK)

typedef unsigned long long ull;

// scratch (allocation-free rule: __device__ globals)
__device__ float g_em[BB * SS * KK];    // emissions
__device__ float g_M[NTILE * 49];       // chunk transfer matrices (log2)
__device__ float g_nump[NTILE];         // numerator partials
__device__ int   g_cntp[NTILE];         // mask-count partials
__device__ unsigned int g_bcnt[BB];     // per-batch chunk completion (wraps)
__device__ unsigned int g_done = 0;     // batch completion (wraps)
__device__ float g_llh = 0.f;           // llh accumulator (self-resetting)

// ---------------------------------------------------------------------------
// fast math helpers
// ---------------------------------------------------------------------------
__device__ __forceinline__ float ex2f(float x) {
    float y; asm("ex2.approx.f32 %0, %1;" : "=f"(y) : "f"(x)); return y;
}
__device__ __forceinline__ float lg2f(float x) {
    float y; asm("lg2.approx.f32 %0, %1;" : "=f"(y) : "f"(x)); return y;
}
__device__ __forceinline__ ull pk2(float lo, float hi) {
    ull r; asm("mov.b64 %0, {%1,%2};" : "=l"(r) : "f"(lo), "f"(hi)); return r;
}
__device__ __forceinline__ void upk2(ull p, float& lo, float& hi) {
    asm("mov.b64 {%0,%1}, %2;" : "=f"(lo), "=f"(hi) : "l"(p));
}
__device__ __forceinline__ ull fma2(ull a, ull b, ull c) {
    ull d; asm("fma.rn.f32x2 %0, %1, %2, %3;" : "=l"(d) : "l"(a), "l"(b), "l"(c));
    return d;
}

// ---------------------------------------------------------------------------
// dtype-width detection (harness may canonicalize bool/int64)
// ---------------------------------------------------------------------------
__device__ __forceinline__ int detect_mask_w(const unsigned char* m) {
    unsigned int or123 = 0, or4 = 0;
#pragma unroll
    for (int off = 0; off < 64; off++) {
        unsigned char v = m[off];
        if (off & 3) or123 |= v;
        else if ((off & 7) == 4) or4 |= v;
    }
    if (or123) return 1;
    return or4 ? 4 : 8;
}
__device__ __forceinline__ int detect_gt_w(const void* gt) {
    const int* v = (const int*)gt;
    int orv = 0;
#pragma unroll
    for (int q = 0; q < 64; q++) orv |= v[2 * q + 1];
    return (orv == 0) ? 2 : 1; // stride in 32-bit words
}

// ---------------------------------------------------------------------------
// K1: pure streaming GEMV. One wave: grid = 4*SMs, block owns contiguous rows
// [lo,hi). 4-deep demand pipeline + L2 prefetch 12 rows ahead.
// ---------------------------------------------------------------------------
__global__ __launch_bounds__(128, 4) void k_emis(const float4* __restrict__ x4,
                                                 const float* __restrict__ W,
                                                 const float* __restrict__ bias,
                                                 int ngrid) {
    const int t = threadIdx.x;
    const int lane = t & 31, warp = t >> 5;
    const unsigned bid = blockIdx.x;
    const int lo = (int)(((ull)bid * 32768ull) / (unsigned)ngrid);
    const int hi = (int)(((ull)(bid + 1) * 32768ull) / (unsigned)ngrid);
    const int n = hi - lo;

    __shared__ float wsum[4][64][8];

    // ---- W slice (56 floats) into registers, packed f32x2 ----
    ull w01[8], w23[8], w45[8];
    float w6[8];
#pragma unroll
    for (int jj = 0; jj < 2; jj++) {
        const float4* wp4 = (const float4*)(W + (t * 4 + jj * 512) * 7);
        float wb[28];
#pragma unroll
        for (int q4 = 0; q4 < 7; q4++) {
            float4 v = wp4[q4];
            wb[q4 * 4 + 0] = v.x; wb[q4 * 4 + 1] = v.y;
            wb[q4 * 4 + 2] = v.z; wb[q4 * 4 + 3] = v.w;
        }
#pragma unroll
        for (int q = 0; q < 4; q++) {
            int s = jj * 4 + q;
            w01[s] = pk2(wb[q * 7 + 0], wb[q * 7 + 1]);
            w23[s] = pk2(wb[q * 7 + 2], wb[q * 7 + 3]);
            w45[s] = pk2(wb[q * 7 + 4], wb[q * 7 + 5]);
            w6[s] = wb[q * 7 + 6];
        }
    }

#define DO_ROW(RR, X0, X1)                                                      \
    {                                                                           \
        float xq[8] = {X0.x, X0.y, X0.z, X0.w, X1.x, X1.y, X1.z, X1.w};         \
        ull c01 = 0, c23 = 0, c45 = 0;                                          \
        float c6 = 0.f;                                                         \
        _Pragma("unroll") for (int s = 0; s < 8; s++) {                         \
            ull xx = pk2(xq[s], xq[s]);                                         \
            c01 = fma2(xx, w01[s], c01);                                        \
            c23 = fma2(xx, w23[s], c23);                                        \
            c45 = fma2(xx, w45[s], c45);                                        \
            c6 = fmaf(xq[s], w6[s], c6);                                        \
        }                                                                       \
        float a[7];                                                             \
        upk2(c01, a[0], a[1]); upk2(c23, a[2], a[3]); upk2(c45, a[4], a[5]);    \
        a[6] = c6;                                                              \
        float tt[7];                                                            \
        _Pragma("unroll") for (int k = 0; k < 7; k++)                           \
            tt[k] = __shfl_xor_sync(0xffffffffu, a[k], 16);                     \
        bool hh = (lane & 16);                                                  \
        float v0 = hh ? a[4] + tt[4] : a[0] + tt[0];                            \
        float v1 = hh ? a[5] + tt[5] : a[1] + tt[1];                            \
        float v2 = hh ? a[6] + tt[6] : a[2] + tt[2];                            \
        float v3 = hh ? 0.f : a[3] + tt[3];                                     \
        float s0 = __shfl_xor_sync(0xffffffffu, v0, 8);                         \
        float s1 = __shfl_xor_sync(0xffffffffu, v1, 8);                         \
        float s2 = __shfl_xor_sync(0xffffffffu, v2, 8);                         \
        float s3 = __shfl_xor_sync(0xffffffffu, v3, 8);                         \
        bool b3p = (lane & 8);                                                  \
        float u0 = b3p ? v2 + s2 : v0 + s0;                                     \
        float u1 = b3p ? v3 + s3 : v1 + s1;                                     \
        float p0 = __shfl_xor_sync(0xffffffffu, u0, 4);                         \
        float p1 = __shfl_xor_sync(0xffffffffu, u1, 4);                         \
        float wv = (lane & 4) ? u1 + p1 : u0 + p0;                              \
        wv += __shfl_xor_sync(0xffffffffu, wv, 2);                              \
        wv += __shfl_xor_sync(0xffffffffu, wv, 1);                              \
        int k7 = (lane >> 2) & 7;                                               \
        if (((lane & 3) == 0) && (k7 < 7)) wsum[warp][RR][k7] = wv;             \
    }

    float4 buf[4][2];
#pragma unroll
    for (int u = 0; u < 4; u++) {
        if (u < n) {
            buf[u][0] = __ldcs(&x4[(long)(lo + u) * 256 + t]);
            buf[u][1] = __ldcs(&x4[(long)(lo + u) * 256 + 128 + t]);
        }
    }

#pragma unroll 1
    for (int rb = 0; rb < n; rb += 4) {
#pragma unroll
        for (int u = 0; u < 4; u++) {
            const int r = rb + u;
            if (r < n) {
                float4 X0 = buf[u][0], X1 = buf[u][1];
                const int pr = r + 4;
                if (pr < n) {
                    buf[u][0] = __ldcs(&x4[(long)(lo + pr) * 256 + t]);
                    buf[u][1] = __ldcs(&x4[(long)(lo + pr) * 256 + 128 + t]);
                }
                if (warp == 0) {
                    const int fr = r + 12;
                    if (fr < n) {
                        const char* p = (const char*)(x4 + (long)(lo + fr) * 256) + lane * 128;
                        asm volatile("prefetch.global.L2 [%0];" :: "l"(p));
                    }
                }
                DO_ROW(r, X0, X1);
            }
        }
    }
#undef DO_ROW
    __syncthreads();
    for (int idx = t; idx < n * 7; idx += 128) {
        int r = idx / 7, k = idx - r * 7;
        g_em[(long)(lo + r) * 7 + k] =
            wsum[0][r][k] + wsum[1][r][k] + wsum[2][r][k] + wsum[3][r][k] + bias[k];
    }
}

// ---------------------------------------------------------------------------
// K2: chunk transfer matrices + numerator partials + elected per-batch combine
// + elected global reduce. grid = (16, 64) x 96 threads.
// ---------------------------------------------------------------------------
__global__ __launch_bounds__(96) void k_chunk(const void* __restrict__ gt,
                                              const unsigned char* __restrict__ mask,
                                              const float* __restrict__ start_t,
                                              const float* __restrict__ end_t,
                                              const float* __restrict__ trans,
                                              float* __restrict__ out) {
    const int c = blockIdx.x, b = blockIdx.y;
    const int tid = threadIdx.x;
    const int lane = tid & 31, warp = tid >> 5;
    const float L2E = 1.4426950408889634f, LN2 = 0.6931471805599453f;

    __shared__ float em_sm[32][8];
    __shared__ int msk_sm[32];
    __shared__ int s_mw, s_gw, s_last;

    if (tid == 0) { s_mw = detect_mask_w(mask); s_gw = detect_gt_w(gt); }

    // cooperative load of this chunk's 224 emission floats (contiguous)
    const float* emb = g_em + ((long)b * SS + c * 32) * 7;
    for (int idx = tid; idx < 224; idx += 96) {
        int lt = idx / 7, k = idx - lt * 7;
        em_sm[lt][k] = emb[idx];
    }
    __syncthreads();
    const int mw = s_mw, gw = s_gw;
    if (tid < 32) msk_sm[tid] = mask[((long)b * SS + c * 32 + tid) * mw] ? 1 : 0;
    __syncthreads();

    // ---- warps 0-1: chunk transfer matrix (scaled forward) ----
    if (warp < 2) {
        const int j = lane & 7;
        const int i = (lane >> 3) + warp * 4;
        const bool act = (j < 7) && (i < 7);
        const int jj = (j < 7) ? j : 0;
        float Tr[7];
#pragma unroll
        for (int k = 0; k < 7; k++)
            Tr[k] = act ? ex2f(trans[k * 7 + jj] * L2E) : 0.f;

        float v = (act && i == j) ? 1.f : 0.f;
        int mexp = 0;
        const int lt0 = (c == 0) ? 1 : 0;
        for (int lt = lt0; lt < 32; lt++) {
            float e = ex2f(em_sm[lt][jj] * L2E);
            int mk = msk_sm[lt];
            float nv = 0.f;
#pragma unroll
            for (int k = 0; k < 7; k++)
                nv = fmaf(__shfl_sync(0xffffffffu, v, k, 8), Tr[k], nv);
            if (mk) v = nv * e;
            if (((lt & 3) == 3) || (lt == 31)) {
                float rs = v;
                rs += __shfl_xor_sync(0xffffffffu, rs, 4, 8);
                rs += __shfl_xor_sync(0xffffffffu, rs, 2, 8);
                rs += __shfl_xor_sync(0xffffffffu, rs, 1, 8);
                int eb = ((__float_as_int(rs) >> 23) & 255) - 127;
                eb = (rs > 0.f) ? eb : 0;
                v *= __int_as_float((127 - eb) << 23); // * 2^-eb
                mexp += eb;
            }
        }
        if (act)
            g_M[((long)(b * 16 + c) * 7 + i) * 7 + j] = (float)mexp + lg2f(v);
    }

    // ---- warp 2: numerator + count partial for this chunk ----
    if (warp == 2) {
        const int s = c * 32 + lane;
        const int m = msk_sm[lane];
        const int gc = ((const int*)gt)[((long)b * SS + s) * gw];
        float contrib;
        if (s == 0) {
            contrib = start_t[gc] + em_sm[0][gc];
        } else {
            const int gp = ((const int*)gt)[((long)b * SS + s - 1) * gw];
            contrib = m ? (trans[gp * 7 + gc] + em_sm[lane][gc]) : 0.f;
        }
        float sum = contrib;
        int cnt = m;
#pragma unroll
        for (int off = 16; off; off >>= 1) {
            sum += __shfl_xor_sync(0xffffffffu, sum, off);
            cnt += __shfl_xor_sync(0xffffffffu, cnt, off);
        }
        if (lane == 0) { g_nump[b * 16 + c] = sum; g_cntp[b * 16 + c] = cnt; }
    }
    __syncthreads();

    // ---- elect per-batch finisher ----
    if (tid == 0) {
        __threadfence();
        unsigned int old = atomicInc(&g_bcnt[b], 15u);
        s_last = (old == 15u) ? 1 : 0;
    }
    __syncthreads();
    if (!s_last || warp != 0) return;

    // ---- batch combine (warp 0 of the finisher) ----
    const int j = lane & 7;
    const int jj = (j < 7) ? j : 0;

    float p = (lane < 16) ? __ldcg(&g_nump[b * 16 + lane]) : 0.f;
    int cn = (lane < 16) ? __ldcg(&g_cntp[b * 16 + lane]) : 0;
#pragma unroll
    for (int off = 16; off; off >>= 1) {
        p += __shfl_xor_sync(0xffffffffu, p, off);
        cn += __shfl_xor_sync(0xffffffffu, cn, off);
    }
    const float num = p + end_t[((const int*)gt)[((long)b * SS + cn - 1) * gw]];

    float a = (j < 7) ? (start_t[jj] + __ldcg(&g_em[(long)b * SS * 7 + jj])) * L2E : -1e30f;
    float M[7], M2[7];
#pragma unroll
    for (int i2 = 0; i2 < 7; i2++)
        M[i2] = __ldcg(&g_M[((long)(b * 16) * 7 + i2) * 7 + jj]);

    for (int cc = 0; cc < NCHUNK; cc++) {
        if (cc + 1 < NCHUNK) {
#pragma unroll
            for (int i2 = 0; i2 < 7; i2++)
                M2[i2] = __ldcg(&g_M[((long)(b * 16 + cc + 1) * 7 + i2) * 7 + jj]);
        }
        float mx = -1e30f;
        float vv[7];
#pragma unroll
        for (int i2 = 0; i2 < 7; i2++) {
            vv[i2] = __shfl_sync(0xffffffffu, a, i2, 8) + M[i2];
            mx = fmaxf(mx, vv[i2]);
        }
        float sum = 0.f;
#pragma unroll
        for (int i2 = 0; i2 < 7; i2++) sum += ex2f(vv[i2] - mx);
        float anew = mx + lg2f(sum);
        a = (j < 7) ? anew : -1e30f;
#pragma unroll
        for (int i2 = 0; i2 < 7; i2++) M[i2] = M2[i2];
    }

    float z = (j < 7) ? a + end_t[jj] * L2E : -1e30f;
    float mz = z;
#pragma unroll
    for (int off = 4; off; off >>= 1)
        mz = fmaxf(mz, __shfl_xor_sync(0xffffffffu, mz, off, 8));
    float se = ex2f(z - mz);
#pragma unroll
    for (int off = 4; off; off >>= 1)
        se += __shfl_xor_sync(0xffffffffu, se, off, 8);
    const float denom = (mz + lg2f(se)) * LN2;

    if (lane == 0) {
        atomicAdd(&g_llh, num - denom);
        __threadfence();
        unsigned int old = atomicInc(&g_done, BB - 1);
        if (old == BB - 1) {
            float tot = atomicExch(&g_llh, 0.f);
            out[0] = -tot / (float)BB;
        }
    }
}

// ---------------------------------------------------------------------------
extern "C" void kernel_launch(void* const* d_in, const int* in_sizes, int n_in,
                              void* d_out, int out_size) {
    const float4* x = (const float4*)d_in[0];
    const void* gt = d_in[1];
    const unsigned char* mask = (const unsigned char*)d_in[2];
    const float* W = (const float*)d_in[3];
    const float* bias = (const float*)d_in[4];
    const float* start_t = (const float*)d_in[5];
    const float* end_t = (const float*)d_in[6];
    const float* trans = (const float*)d_in[7];
    float* out = (float*)d_out;

    int smc = 148;
    cudaDeviceGetAttribute(&smc, cudaDevAttrMultiProcessorCount, 0);
    const int grid = smc * 4;

    k_emis<<<grid, 128>>>(x, W, bias, grid);
    dim3 g2(16, 64);
    k_chunk<<<g2, 96>>>(gt, mask, start_t, end_t, trans, out);
}

// round 7
// speedup vs baseline: 1.3515x; 1.0934x over previous
#include <cuda_runtime.h>

#define BB 64
#define SS 512
#define HH 1024
#define KK 7
#define NCHUNK 16

typedef unsigned long long ull;

// scratch (allocation-free rule: __device__ globals)
__device__ float g_em[BB * SS * KK];    // emissions
__device__ unsigned int g_done = 0;     // batch completion (wraps)
__device__ float g_llh = 0.f;           // llh accumulator (self-resetting)

// ---------------------------------------------------------------------------
// fast math helpers
// ---------------------------------------------------------------------------
__device__ __forceinline__ float ex2f(float x) {
    float y; asm("ex2.approx.f32 %0, %1;" : "=f"(y) : "f"(x)); return y;
}
__device__ __forceinline__ float lg2f(float x) {
    float y; asm("lg2.approx.f32 %0, %1;" : "=f"(y) : "f"(x)); return y;
}
__device__ __forceinline__ ull pk2(float lo, float hi) {
    ull r; asm("mov.b64 %0, {%1,%2};" : "=l"(r) : "f"(lo), "f"(hi)); return r;
}
__device__ __forceinline__ void upk2(ull p, float& lo, float& hi) {
    asm("mov.b64 {%0,%1}, %2;" : "=f"(lo), "=f"(hi) : "l"(p));
}
__device__ __forceinline__ ull fma2(ull a, ull b, ull c) {
    ull d; asm("fma.rn.f32x2 %0, %1, %2, %3;" : "=l"(d) : "l"(a), "l"(b), "l"(c));
    return d;
}

// ---------------------------------------------------------------------------
// dtype-width detection (harness may canonicalize bool/int64)
// ---------------------------------------------------------------------------
__device__ __forceinline__ int detect_mask_w(const unsigned char* m) {
    unsigned int or123 = 0, or4 = 0;
#pragma unroll
    for (int off = 0; off < 64; off++) {
        unsigned char v = m[off];
        if (off & 3) or123 |= v;
        else if ((off & 7) == 4) or4 |= v;
    }
    if (or123) return 1;
    return or4 ? 4 : 8;
}
__device__ __forceinline__ int detect_gt_w(const void* gt) {
    const int* v = (const int*)gt;
    int orv = 0;
#pragma unroll
    for (int q = 0; q < 64; q++) orv |= v[2 * q + 1];
    return (orv == 0) ? 2 : 1; // stride in 32-bit words
}

// ---------------------------------------------------------------------------
// K1: pure streaming GEMV (unchanged from round 6: best-known config).
// ---------------------------------------------------------------------------
__global__ __launch_bounds__(128, 4) void k_emis(const float4* __restrict__ x4,
                                                 const float* __restrict__ W,
                                                 const float* __restrict__ bias,
                                                 int ngrid) {
    const int t = threadIdx.x;
    const int lane = t & 31, warp = t >> 5;
    const unsigned bid = blockIdx.x;
    const int lo = (int)(((ull)bid * 32768ull) / (unsigned)ngrid);
    const int hi = (int)(((ull)(bid + 1) * 32768ull) / (unsigned)ngrid);
    const int n = hi - lo;

    __shared__ float wsum[4][64][8];

    ull w01[8], w23[8], w45[8];
    float w6[8];
#pragma unroll
    for (int jj = 0; jj < 2; jj++) {
        const float4* wp4 = (const float4*)(W + (t * 4 + jj * 512) * 7);
        float wb[28];
#pragma unroll
        for (int q4 = 0; q4 < 7; q4++) {
            float4 v = wp4[q4];
            wb[q4 * 4 + 0] = v.x; wb[q4 * 4 + 1] = v.y;
            wb[q4 * 4 + 2] = v.z; wb[q4 * 4 + 3] = v.w;
        }
#pragma unroll
        for (int q = 0; q < 4; q++) {
            int s = jj * 4 + q;
            w01[s] = pk2(wb[q * 7 + 0], wb[q * 7 + 1]);
            w23[s] = pk2(wb[q * 7 + 2], wb[q * 7 + 3]);
            w45[s] = pk2(wb[q * 7 + 4], wb[q * 7 + 5]);
            w6[s] = wb[q * 7 + 6];
        }
    }

#define DO_ROW(RR, X0, X1)                                                      \
    {                                                                           \
        float xq[8] = {X0.x, X0.y, X0.z, X0.w, X1.x, X1.y, X1.z, X1.w};         \
        ull c01 = 0, c23 = 0, c45 = 0;                                          \
        float c6 = 0.f;                                                         \
        _Pragma("unroll") for (int s = 0; s < 8; s++) {                         \
            ull xx = pk2(xq[s], xq[s]);                                         \
            c01 = fma2(xx, w01[s], c01);                                        \
            c23 = fma2(xx, w23[s], c23);                                        \
            c45 = fma2(xx, w45[s], c45);                                        \
            c6 = fmaf(xq[s], w6[s], c6);                                        \
        }                                                                       \
        float a[7];                                                             \
        upk2(c01, a[0], a[1]); upk2(c23, a[2], a[3]); upk2(c45, a[4], a[5]);    \
        a[6] = c6;                                                              \
        float tt[7];                                                            \
        _Pragma("unroll") for (int k = 0; k < 7; k++)                           \
            tt[k] = __shfl_xor_sync(0xffffffffu, a[k], 16);                     \
        bool hh = (lane & 16);                                                  \
        float v0 = hh ? a[4] + tt[4] : a[0] + tt[0];                            \
        float v1 = hh ? a[5] + tt[5] : a[1] + tt[1];                            \
        float v2 = hh ? a[6] + tt[6] : a[2] + tt[2];                            \
        float v3 = hh ? 0.f : a[3] + tt[3];                                     \
        float s0 = __shfl_xor_sync(0xffffffffu, v0, 8);                         \
        float s1 = __shfl_xor_sync(0xffffffffu, v1, 8);                         \
        float s2 = __shfl_xor_sync(0xffffffffu, v2, 8);                         \
        float s3 = __shfl_xor_sync(0xffffffffu, v3, 8);                         \
        bool b3p = (lane & 8);                                                  \
        float u0 = b3p ? v2 + s2 : v0 + s0;                                     \
        float u1 = b3p ? v3 + s3 : v1 + s1;                                     \
        float p0 = __shfl_xor_sync(0xffffffffu, u0, 4);                         \
        float p1 = __shfl_xor_sync(0xffffffffu, u1, 4);                         \
        float wv = (lane & 4) ? u1 + p1 : u0 + p0;                              \
        wv += __shfl_xor_sync(0xffffffffu, wv, 2);                              \
        wv += __shfl_xor_sync(0xffffffffu, wv, 1);                              \
        int k7 = (lane >> 2) & 7;                                               \
        if (((lane & 3) == 0) && (k7 < 7)) wsum[warp][RR][k7] = wv;             \
    }

    float4 buf[4][2];
#pragma unroll
    for (int u = 0; u < 4; u++) {
        if (u < n) {
            buf[u][0] = __ldcs(&x4[(long)(lo + u) * 256 + t]);
            buf[u][1] = __ldcs(&x4[(long)(lo + u) * 256 + 128 + t]);
        }
    }

#pragma unroll 1
    for (int rb = 0; rb < n; rb += 4) {
#pragma unroll
        for (int u = 0; u < 4; u++) {
            const int r = rb + u;
            if (r < n) {
                float4 X0 = buf[u][0], X1 = buf[u][1];
                const int pr = r + 4;
                if (pr < n) {
                    buf[u][0] = __ldcs(&x4[(long)(lo + pr) * 256 + t]);
                    buf[u][1] = __ldcs(&x4[(long)(lo + pr) * 256 + 128 + t]);
                }
                if (warp == 0) {
                    const int fr = r + 12;
                    if (fr < n) {
                        const char* p = (const char*)(x4 + (long)(lo + fr) * 256) + lane * 128;
                        asm volatile("prefetch.global.L2 [%0];" :: "l"(p));
                    }
                }
                DO_ROW(r, X0, X1);
            }
        }
    }
#undef DO_ROW
    __syncthreads();
    for (int idx = t; idx < n * 7; idx += 128) {
        int r = idx / 7, k = idx - r * 7;
        g_em[(long)(lo + r) * 7 + k] =
            wsum[0][r][k] + wsum[1][r][k] + wsum[2][r][k] + wsum[3][r][k] + bias[k];
    }
}

// ---------------------------------------------------------------------------
// K2: one block per batch. Register-resident 7x7 recursion (no shuffles),
// in-block combine + numerator, atomic-elected final writer.
// eexp layout: chunk c at word base 260*c (bank skew 4c -> conflict-free).
// ---------------------------------------------------------------------------
__global__ __launch_bounds__(128) void k_batch(const void* __restrict__ gt,
                                               const unsigned char* __restrict__ mask,
                                               const float* __restrict__ start_t,
                                               const float* __restrict__ end_t,
                                               const float* __restrict__ trans,
                                               float* __restrict__ out) {
    const int b = blockIdx.x;
    const int tid = threadIdx.x;
    const int lane = tid & 31, warp = tid >> 5;
    const float L2E = 1.4426950408889634f, LN2 = 0.6931471805599453f;

    __shared__ float eexp[4160];      // 2^(em*L2E), skewed: idx = t*8+((t>>5)<<2)+k
    __shared__ int msk_sm[SS];
    __shared__ float trans_s[49];
    __shared__ float Msh[NCHUNK][52];
    __shared__ float s_red[4];
    __shared__ int s_cnt4[4];
    __shared__ float s_num;
    __shared__ int s_mw, s_gw;

    if (tid == 0) { s_mw = detect_mask_w(mask); s_gw = detect_gt_w(gt); }
    if (tid < 49) trans_s[tid] = trans[tid];
    __syncthreads();
    const int mw = s_mw, gw = s_gw;

    // ---- stage emissions (exp2'd) + mask into smem ----
    const float* emb = g_em + (long)b * SS * 7;
#pragma unroll
    for (int pass = 0; pass < 32; pass++) {
        int idx = pass * 128 + tid;          // 0..4095
        int t = idx >> 3, k = idx & 7;
        float val = 0.f;
        if (k < 7) val = ex2f(emb[t * 7 + k] * L2E);
        eexp[t * 8 + ((t >> 5) << 2) + k] = val;
    }
#pragma unroll
    for (int pass = 0; pass < 4; pass++) {
        int idx = pass * 128 + tid;
        msk_sm[idx] = mask[((long)b * SS + idx) * mw] ? 1 : 0;
    }
    __syncthreads();

    // ---- numerator partial: 4 timesteps per thread ----
    float ns = 0.f;
    int nc = 0;
#pragma unroll
    for (int q = 0; q < 4; q++) {
        int t = tid * 4 + q;
        int gc = ((const int*)gt)[((long)b * SS + t) * gw];
        int m = msk_sm[t];
        nc += m;
        float emv = lg2f(eexp[t * 8 + ((t >> 5) << 2) + gc]) * LN2;
        if (t == 0) {
            ns += start_t[gc] + emv;
        } else {
            int gp = ((const int*)gt)[((long)b * SS + t - 1) * gw];
            ns += m ? (trans_s[gp * 7 + gc] + emv) : 0.f;
        }
    }
#pragma unroll
    for (int off = 16; off; off >>= 1) {
        ns += __shfl_xor_sync(0xffffffffu, ns, off);
        nc += __shfl_xor_sync(0xffffffffu, nc, off);
    }
    if (lane == 0) { s_red[warp] = ns; s_cnt4[warp] = nc; }

    // ---- recursion: thread (c,i) advances row i of chunk c, all in registers
    if (tid < 112) {
        const int c = tid / 7;
        const int i = tid - c * 7;

        float Trx[49];
#pragma unroll
        for (int z = 0; z < 49; z++) Trx[z] = ex2f(trans_s[z] * L2E);

        float v[7];
#pragma unroll
        for (int j = 0; j < 7; j++) v[j] = (i == j) ? 1.f : 0.f;
        int mexp = 0;
        const int ebase = c * 260;   // chunk base in eexp
        const int t0 = c * 32;

#pragma unroll 1
        for (int g4 = 0; g4 < 8; g4++) {
#pragma unroll
            for (int q = 0; q < 4; q++) {
                const int lt = g4 * 4 + q;
                const int t = t0 + lt;
                float4 e0 = *(const float4*)&eexp[ebase + lt * 8];
                float4 e1 = *(const float4*)&eexp[ebase + lt * 8 + 4];
                int mk = msk_sm[t];
                if (t == 0) mk = 0;   // chunk 0 starts at step 1
                float nv[7];
#pragma unroll
                for (int j = 0; j < 7; j++) nv[j] = v[0] * Trx[j];
#pragma unroll
                for (int k = 1; k < 7; k++)
#pragma unroll
                    for (int j = 0; j < 7; j++)
                        nv[j] = fmaf(v[k], Trx[k * 7 + j], nv[j]);
                if (mk) {
                    v[0] = nv[0] * e0.x; v[1] = nv[1] * e0.y;
                    v[2] = nv[2] * e0.z; v[3] = nv[3] * e0.w;
                    v[4] = nv[4] * e1.x; v[5] = nv[5] * e1.y;
                    v[6] = nv[6] * e1.z;
                }
            }
            // renorm (per 4 steps): pull out row-sum exponent
            float rs = ((v[0] + v[1]) + (v[2] + v[3])) + ((v[4] + v[5]) + v[6]);
            int eb = ((__float_as_int(rs) >> 23) & 255) - 127;
            eb = (rs > 0.f) ? eb : 0;
            float scl = __int_as_float((127 - eb) << 23);  // 2^-eb
#pragma unroll
            for (int j = 0; j < 7; j++) v[j] *= scl;
            mexp += eb;
        }
#pragma unroll
        for (int j = 0; j < 7; j++)
            Msh[c][i * 7 + j] = (float)mexp + lg2f(v[j]);
    }
    __syncthreads();

    if (tid == 0) {
        float p = s_red[0] + s_red[1] + s_red[2] + s_red[3];
        int ct = s_cnt4[0] + s_cnt4[1] + s_cnt4[2] + s_cnt4[3];
        s_num = p + end_t[((const int*)gt)[((long)b * SS + ct - 1) * gw]];
    }
    __syncthreads();

    // ---- combine: warp 0, 8-lane groups (redundant across groups) ----
    if (warp == 0) {
        const int j = lane & 7;
        const int jj = (j < 7) ? j : 0;
        float a = (j < 7) ? start_t[jj] * L2E + lg2f(eexp[jj]) : -1e30f;

        for (int cc = 0; cc < NCHUNK; cc++) {
            float mx = -1e30f;
            float vv[7];
#pragma unroll
            for (int i2 = 0; i2 < 7; i2++) {
                vv[i2] = __shfl_sync(0xffffffffu, a, i2, 8) + Msh[cc][i2 * 7 + jj];
                mx = fmaxf(mx, vv[i2]);
            }
            float sum = 0.f;
#pragma unroll
            for (int i2 = 0; i2 < 7; i2++) sum += ex2f(vv[i2] - mx);
            float anew = mx + lg2f(sum);
            a = (j < 7) ? anew : -1e30f;
        }

        float z = (j < 7) ? a + end_t[jj] * L2E : -1e30f;
        float mz = z;
#pragma unroll
        for (int off = 4; off; off >>= 1)
            mz = fmaxf(mz, __shfl_xor_sync(0xffffffffu, mz, off, 8));
        float se = ex2f(z - mz);
#pragma unroll
        for (int off = 4; off; off >>= 1)
            se += __shfl_xor_sync(0xffffffffu, se, off, 8);
        const float denom = (mz + lg2f(se)) * LN2;

        if (lane == 0) {
            atomicAdd(&g_llh, s_num - denom);
            __threadfence();
            unsigned int old = atomicInc(&g_done, BB - 1);
            if (old == BB - 1) {
                float tot = atomicExch(&g_llh, 0.f);
                out[0] = -tot / (float)BB;
            }
        }
    }
}

// ---------------------------------------------------------------------------
extern "C" void kernel_launch(void* const* d_in, const int* in_sizes, int n_in,
                              void* d_out, int out_size) {
    const float4* x = (const float4*)d_in[0];
    const void* gt = d_in[1];
    const unsigned char* mask = (const unsigned char*)d_in[2];
    const float* W = (const float*)d_in[3];
    const float* bias = (const float*)d_in[4];
    const float* start_t = (const float*)d_in[5];
    const float* end_t = (const float*)d_in[6];
    const float* trans = (const float*)d_in[7];
    float* out = (float*)d_out;

    int smc = 148;
    cudaDeviceGetAttribute(&smc, cudaDevAttrMultiProcessorCount, 0);
    const int grid = smc * 4;

    k_emis<<<grid, 128>>>(x, W, bias, grid);
    k_batch<<<BB, 128>>>(gt, mask, start_t, end_t, trans, out);
}